// round 9
// baseline (speedup 1.0000x reference)
#include <cuda_runtime.h>
#include <math.h>

#define NN 50000
#define NE 1600000
#define HH 4
#define FF 128
#define NBLK 49                 // ceil(50000/1024)
#define NODE_BLOCKS 6250        // NN*32/256
#define HIST_BLOCKS 3125        // (NE/2)/256 int4-loads

typedef unsigned long long u64;

// ---------------- scratch ----------------------------------------------------
__device__ int       g_is64;
__device__ int       g_deg[NN];        // zero at load; re-zeroed by k_scatter each call
__device__ int       g_off[NN + 1];
__device__ int       g_cursor[NN];
__device__ float4    g_ssrc[NN];
__device__ float4    g_sdst[NN];
__device__ ulonglong2 g_wd[2 * (size_t)NE];   // per edge: {dup(w0),dup(w1)},{dup(w2),dup(w3)}
__device__ int       g_dst[NE + 8];           // padded for prefetch over-read

// ---------------- f32x2 helpers ----------------------------------------------
__device__ __forceinline__ u64 pack2(float a, float b) {
    u64 r; asm("mov.b64 %0,{%1,%2};" : "=l"(r) : "f"(a), "f"(b)); return r;
}
__device__ __forceinline__ void unpk2(u64 v, float& a, float& b) {
    asm("mov.b64 {%0,%1},%2;" : "=f"(a), "=f"(b) : "l"(v));
}
__device__ __forceinline__ u64 ffma2(u64 a, u64 b, u64 c) {
    u64 d; asm("fma.rn.f32x2 %0,%1,%2,%3;" : "=l"(d) : "l"(a), "l"(b), "l"(c)); return d;
}
__device__ __forceinline__ u64 fadd2(u64 a, u64 b) {
    u64 d; asm("add.rn.f32x2 %0,%1,%2;" : "=l"(d) : "l"(a), "l"(b)); return d;
}

// ---------------- 1) fused prep (scores + detect) & hist ---------------------
__global__ void __launch_bounds__(256) k_prep(const float* __restrict__ x,
                                              const float* __restrict__ wp,
                                              const float* __restrict__ ap,
                                              const int* __restrict__ ei) {
    int b = blockIdx.x;
    if (b >= NODE_BLOCKS) {
        // histogram: coalesced int4 over the src array
        int t = (b - NODE_BLOCKS) * 256 + threadIdx.x;   // int4 index < NE/2
        int4 v = ((const int4*)ei)[t];
        __shared__ int any32;
        if (threadIdx.x == 0) any32 = 0;
        __syncthreads();
        if ((v.y | v.w) != 0) any32 = 1;
        __syncthreads();
        if (any32 == 0) {                 // int64 layout
            atomicAdd(&g_deg[v.x], 1);
            atomicAdd(&g_deg[v.z], 1);
        } else if (t < NE / 4) {          // int32 layout
            atomicAdd(&g_deg[v.x], 1);
            atomicAdd(&g_deg[v.y], 1);
            atomicAdd(&g_deg[v.z], 1);
            atomicAdd(&g_deg[v.w], 1);
        }
        return;
    }

    int tid = b * 256 + threadIdx.x;
    if (tid == 0) g_off[NN] = NE;
    if (b == 0) {
        __shared__ int bad;
        if (threadIdx.x == 0) bad = 0;
        __syncthreads();
        for (int k = threadIdx.x; k < 4096; k += 256)
            if (ei[2 * k + 1] != 0) bad = 1;
        __syncthreads();
        if (threadIdx.x == 0) g_is64 = (bad == 0) ? 1 : 0;
    }

    int gw   = tid >> 5;
    int lane = threadIdx.x & 31;
    int f = lane * 4;
    float4 xv = *(const float4*)(x + (size_t)gw * FF + f);

    float ss[HH], sd[HH];
    #pragma unroll
    for (int h = 0; h < HH; h++) {
        float4 wv = *(const float4*)(wp + h * FF + f);
        float4 as = *(const float4*)(ap + h * 2 * FF + f);
        float4 ad = *(const float4*)(ap + h * 2 * FF + FF + f);
        float4 hw = make_float4(xv.x * wv.x, xv.y * wv.y, xv.z * wv.z, xv.w * wv.w);
        float hs = hw.x * as.x + hw.y * as.y + hw.z * as.z + hw.w * as.w;
        float hd = hw.x * ad.x + hw.y * ad.y + hw.z * ad.z + hw.w * ad.w;
        #pragma unroll
        for (int o = 16; o; o >>= 1) {
            hs += __shfl_xor_sync(0xffffffffu, hs, o);
            hd += __shfl_xor_sync(0xffffffffu, hd, o);
        }
        ss[h] = hs; sd[h] = hd;
    }
    if (lane == 0) {
        g_ssrc[gw] = make_float4(ss[0], ss[1], ss[2], ss[3]);
        g_sdst[gw] = make_float4(sd[0], sd[1], sd[2], sd[3]);
    }
}

// ---------------- 2) one-shot scan -------------------------------------------
__global__ void k_scan() {
    __shared__ int wsum[32];
    __shared__ int redsum[32];
    int b = blockIdx.x, t = threadIdx.x, lane = t & 31, wid = t >> 5;

    int pre = b * 1024;
    int acc = 0;
    for (int i = t; i < pre; i += 1024) acc += g_deg[i];
    #pragma unroll
    for (int o = 16; o; o >>= 1) acc += __shfl_xor_sync(0xffffffffu, acc, o);
    if (lane == 0) redsum[wid] = acc;
    __syncthreads();
    int bofs;
    {
        int v = redsum[lane];
        #pragma unroll
        for (int o = 16; o; o >>= 1) v += __shfl_xor_sync(0xffffffffu, v, o);
        bofs = __shfl_sync(0xffffffffu, v, 0);
    }

    int i = pre + t;
    int v = (i < NN) ? g_deg[i] : 0;
    int inc = v;
    #pragma unroll
    for (int o = 1; o < 32; o <<= 1) {
        int u = __shfl_up_sync(0xffffffffu, inc, o);
        if (lane >= o) inc += u;
    }
    if (lane == 31) wsum[wid] = inc;
    __syncthreads();
    if (wid == 0) {
        int s = wsum[lane];
        #pragma unroll
        for (int o = 1; o < 32; o <<= 1) {
            int u = __shfl_up_sync(0xffffffffu, s, o);
            if (lane >= o) s += u;
        }
        wsum[lane] = s;
    }
    __syncthreads();
    int excl = bofs + (wid ? wsum[wid - 1] : 0) + inc - v;
    if (i < NN) { g_off[i] = excl; g_cursor[i] = excl; }
}

// ---------------- 3) scatter: fp32 pre-duplicated weight records -------------
__device__ __forceinline__ float edge_w(float s) {
    return __expf(fminf(-s, -0.2f * s));   // exp(-leaky_relu(s, 0.2))
}
__global__ void __launch_bounds__(256) k_scatter(const int* __restrict__ ei) {
    int i = blockIdx.x * blockDim.x + threadIdx.x;
    if (i < NN) g_deg[i] = 0;              // restore invariant for next call
    if (i >= NE / 2) return;               // 2 edges per thread
    int s0, s1, d0, d1;
    if (g_is64) {
        int4 sv = ((const int4*)ei)[i];
        int4 dv = ((const int4*)ei)[NE / 2 + i];
        s0 = sv.x; s1 = sv.z; d0 = dv.x; d1 = dv.z;
    } else {
        int2 sv = ((const int2*)ei)[i];
        int2 dv = ((const int2*)ei)[NE / 2 + i];
        s0 = sv.x; s1 = sv.y; d0 = dv.x; d1 = dv.y;
    }
    float4 a0 = g_ssrc[s0], b0 = g_sdst[d0];
    float4 a1 = g_ssrc[s1], b1 = g_sdst[d1];

    float w00 = edge_w(a0.x + b0.x), w01 = edge_w(a0.y + b0.y);
    float w02 = edge_w(a0.z + b0.z), w03 = edge_w(a0.w + b0.w);
    float w10 = edge_w(a1.x + b1.x), w11 = edge_w(a1.y + b1.y);
    float w12 = edge_w(a1.z + b1.z), w13 = edge_w(a1.w + b1.w);

    int p0 = atomicAdd(&g_cursor[s0], 1);
    int p1 = atomicAdd(&g_cursor[s1], 1);

    g_wd[2 * (size_t)p0]     = make_ulonglong2(pack2(w00, w00), pack2(w01, w01));
    g_wd[2 * (size_t)p0 + 1] = make_ulonglong2(pack2(w02, w02), pack2(w03, w03));
    g_dst[p0] = d0;
    g_wd[2 * (size_t)p1]     = make_ulonglong2(pack2(w10, w10), pack2(w11, w11));
    g_wd[2 * (size_t)p1 + 1] = make_ulonglong2(pack2(w12, w12), pack2(w13, w13));
    g_dst[p1] = d1;
}

// ---------------- 4) aggregation: fp32 x, pre-dup weights, chunk-4 -----------
__device__ __forceinline__ void edge_math(u64 p0, u64 p1, u64 p2, u64 p3,
                                          u64 xv01, u64 xv23,
                                          u64 acc[HH][2],
                                          u64& rsA, u64& rsB, u64& rsC, u64& rsD) {
    rsA = fadd2(rsA, p0); rsB = fadd2(rsB, p1);
    rsC = fadd2(rsC, p2); rsD = fadd2(rsD, p3);
    acc[0][0] = ffma2(p0, xv01, acc[0][0]); acc[0][1] = ffma2(p0, xv23, acc[0][1]);
    acc[1][0] = ffma2(p1, xv01, acc[1][0]); acc[1][1] = ffma2(p1, xv23, acc[1][1]);
    acc[2][0] = ffma2(p2, xv01, acc[2][0]); acc[2][1] = ffma2(p2, xv23, acc[2][1]);
    acc[3][0] = ffma2(p3, xv01, acc[3][0]); acc[3][1] = ffma2(p3, xv23, acc[3][1]);
}

__global__ void __launch_bounds__(256, 4) k_agg(const float* __restrict__ x,
                                                const float* __restrict__ wp,
                                                float* __restrict__ out) {
    int gw   = (blockIdx.x * blockDim.x + threadIdx.x) >> 5;
    int lane = threadIdx.x & 31;
    if (gw >= NN) return;
    int beg = g_off[gw];
    int n   = g_off[gw + 1] - beg;
    int f = lane * 4;
    const int* dp = g_dst + beg;
    const ulonglong2* wdp = g_wd + 2 * (size_t)beg;

    u64 acc[HH][2];
    #pragma unroll
    for (int h = 0; h < HH; h++) { acc[h][0] = 0ull; acc[h][1] = 0ull; }
    u64 rsA = 0ull, rsB = 0ull, rsC = 0ull, rsD = 0ull;

    int dstc[4];
    #pragma unroll
    for (int k = 0; k < 4; k++) dstc[k] = __ldcs(dp + k);   // padded array: safe

    int nfull = n & ~3;
    for (int c = 0; c < nfull; c += 4) {
        // 4 independent fp32 x gathers (16B each)
        ulonglong2 xr[4];
        #pragma unroll
        for (int k = 0; k < 4; k++)
            xr[k] = __ldg((const ulonglong2*)(x + (size_t)dstc[k] * FF + f));
        // prefetch next chunk's dsts (over-read is padded / unused)
        #pragma unroll
        for (int k = 0; k < 4; k++) dstc[k] = __ldcs(dp + c + 4 + k);
        // math: weights loaded broadcast, L1-hot (1 line = 4 edges)
        #pragma unroll
        for (int k = 0; k < 4; k++) {
            ulonglong2 wa = __ldcs(wdp + 2 * (c + k));
            ulonglong2 wb = __ldcs(wdp + 2 * (c + k) + 1);
            edge_math(wa.x, wa.y, wb.x, wb.y, xr[k].x, xr[k].y, acc, rsA, rsB, rsC, rsD);
        }
    }
    // tail (dstc already holds dsts for [nfull, nfull+4))
    #pragma unroll
    for (int k = 0; k < 3; k++) {
        if (nfull + k < n) {
            ulonglong2 xv = __ldg((const ulonglong2*)(x + (size_t)dstc[k] * FF + f));
            ulonglong2 wa = __ldcs(wdp + 2 * (nfull + k));
            ulonglong2 wb = __ldcs(wdp + 2 * (nfull + k) + 1);
            edge_math(wa.x, wa.y, wb.x, wb.y, xv.x, xv.y, acc, rsA, rsB, rsC, rsD);
        }
    }

    float rs0, rs1, rs2, rs3, junk;
    unpk2(rsA, rs0, junk); unpk2(rsB, rs1, junk);
    unpk2(rsC, rs2, junk); unpk2(rsD, rs3, junk);
    float inv[HH] = {1.0f / rs0, 1.0f / rs1, 1.0f / rs2, 1.0f / rs3};

    size_t base = (size_t)gw * FF + f;
    #pragma unroll
    for (int h = 0; h < HH; h++) {
        float4 wv = *(const float4*)(wp + h * FF + f);
        float a0, a1, a2, a3;
        unpk2(acc[h][0], a0, a1); unpk2(acc[h][1], a2, a3);
        __stcs((float4*)(out + (size_t)h * NN * FF + base),
            make_float4(a0 * wv.x * inv[h], a1 * wv.y * inv[h],
                        a2 * wv.z * inv[h], a3 * wv.w * inv[h]));
    }
}

// ---------------- launch -----------------------------------------------------
extern "C" void kernel_launch(void* const* d_in, const int* in_sizes, int n_in,
                              void* d_out, int out_size) {
    const float* x  = (const float*)d_in[0];
    const float* wp = (const float*)d_in[1];
    const float* ap = (const float*)d_in[2];
    const int*   ei = (const int*)d_in[3];
    float* out = (float*)d_out;

    const int TB = 256;
    k_prep<<<NODE_BLOCKS + HIST_BLOCKS, TB>>>(x, wp, ap, ei);
    k_scan<<<NBLK, 1024>>>();
    k_scatter<<<(NE / 2 + TB - 1) / TB, TB>>>(ei);
    k_agg<<<NODE_BLOCKS, TB>>>(x, wp, out);
}

// round 10
// speedup vs baseline: 1.3798x; 1.3798x over previous
#include <cuda_runtime.h>
#include <cuda_fp16.h>
#include <math.h>

#define NN 50000
#define NE 1600000
#define HH 4
#define FF 128
#define NBLK 49                 // ceil(50000/1024)
#define NODE_BLOCKS 6250        // NN*32/256
#define HIST_BLOCKS 3125        // (NE/2)/256 int4-loads

typedef unsigned long long u64;

// ---------------- scratch ----------------------------------------------------
__device__ int    g_is64;
__device__ int    g_deg[NN];          // zero at load; re-zeroed by k_scatter each call
__device__ int    g_off[NN + 1];
__device__ int    g_cursor[NN];
__device__ float4 g_ssrc[NN];
__device__ float4 g_sdst[NN];
__device__ int4   g_edges[NE];        // {half2 w01, half2 w23, dst, pad}

// ---------------- f32x2 helpers ----------------------------------------------
__device__ __forceinline__ u64 pack2(float a, float b) {
    u64 r; asm("mov.b64 %0,{%1,%2};" : "=l"(r) : "f"(a), "f"(b)); return r;
}
__device__ __forceinline__ u64 dup2(float a) { return pack2(a, a); }
__device__ __forceinline__ void unpk2(u64 v, float& a, float& b) {
    asm("mov.b64 {%0,%1},%2;" : "=f"(a), "=f"(b) : "l"(v));
}
__device__ __forceinline__ u64 ffma2(u64 a, u64 b, u64 c) {
    u64 d; asm("fma.rn.f32x2 %0,%1,%2,%3;" : "=l"(d) : "l"(a), "l"(b), "l"(c)); return d;
}
__device__ __forceinline__ u64 fadd2(u64 a, u64 b) {
    u64 d; asm("add.rn.f32x2 %0,%1,%2;" : "=l"(d) : "l"(a), "l"(b)); return d;
}

// ---------------- 1) fused prep (scores + detect) & hist ---------------------
__global__ void __launch_bounds__(256) k_prep(const float* __restrict__ x,
                                              const float* __restrict__ wp,
                                              const float* __restrict__ ap,
                                              const int* __restrict__ ei) {
    int b = blockIdx.x;
    if (b >= NODE_BLOCKS) {
        // histogram: coalesced int4 over the src array
        int t = (b - NODE_BLOCKS) * 256 + threadIdx.x;   // int4 index < NE/2
        int4 v = ((const int4*)ei)[t];
        __shared__ int any32;
        if (threadIdx.x == 0) any32 = 0;
        __syncthreads();
        if ((v.y | v.w) != 0) any32 = 1;
        __syncthreads();
        if (any32 == 0) {                 // int64 layout
            atomicAdd(&g_deg[v.x], 1);
            atomicAdd(&g_deg[v.z], 1);
        } else if (t < NE / 4) {          // int32 layout
            atomicAdd(&g_deg[v.x], 1);
            atomicAdd(&g_deg[v.y], 1);
            atomicAdd(&g_deg[v.z], 1);
            atomicAdd(&g_deg[v.w], 1);
        }
        return;
    }

    int tid = b * 256 + threadIdx.x;
    if (tid == 0) g_off[NN] = NE;
    if (b == 0) {
        __shared__ int bad;
        if (threadIdx.x == 0) bad = 0;
        __syncthreads();
        for (int k = threadIdx.x; k < 4096; k += 256)
            if (ei[2 * k + 1] != 0) bad = 1;
        __syncthreads();
        if (threadIdx.x == 0) g_is64 = (bad == 0) ? 1 : 0;
    }

    int gw   = tid >> 5;
    int lane = threadIdx.x & 31;
    int f = lane * 4;
    float4 xv = *(const float4*)(x + (size_t)gw * FF + f);

    float ss[HH], sd[HH];
    #pragma unroll
    for (int h = 0; h < HH; h++) {
        float4 wv = *(const float4*)(wp + h * FF + f);
        float4 as = *(const float4*)(ap + h * 2 * FF + f);
        float4 ad = *(const float4*)(ap + h * 2 * FF + FF + f);
        float4 hw = make_float4(xv.x * wv.x, xv.y * wv.y, xv.z * wv.z, xv.w * wv.w);
        float hs = hw.x * as.x + hw.y * as.y + hw.z * as.z + hw.w * as.w;
        float hd = hw.x * ad.x + hw.y * ad.y + hw.z * ad.z + hw.w * ad.w;
        #pragma unroll
        for (int o = 16; o; o >>= 1) {
            hs += __shfl_xor_sync(0xffffffffu, hs, o);
            hd += __shfl_xor_sync(0xffffffffu, hd, o);
        }
        ss[h] = hs; sd[h] = hd;
    }
    if (lane == 0) {
        g_ssrc[gw] = make_float4(ss[0], ss[1], ss[2], ss[3]);
        g_sdst[gw] = make_float4(sd[0], sd[1], sd[2], sd[3]);
    }
}

// ---------------- 2) one-shot scan -------------------------------------------
__global__ void k_scan() {
    __shared__ int wsum[32];
    __shared__ int redsum[32];
    int b = blockIdx.x, t = threadIdx.x, lane = t & 31, wid = t >> 5;

    int pre = b * 1024;
    int acc = 0;
    for (int i = t; i < pre; i += 1024) acc += g_deg[i];
    #pragma unroll
    for (int o = 16; o; o >>= 1) acc += __shfl_xor_sync(0xffffffffu, acc, o);
    if (lane == 0) redsum[wid] = acc;
    __syncthreads();
    int bofs;
    {
        int v = redsum[lane];
        #pragma unroll
        for (int o = 16; o; o >>= 1) v += __shfl_xor_sync(0xffffffffu, v, o);
        bofs = __shfl_sync(0xffffffffu, v, 0);
    }

    int i = pre + t;
    int v = (i < NN) ? g_deg[i] : 0;
    int inc = v;
    #pragma unroll
    for (int o = 1; o < 32; o <<= 1) {
        int u = __shfl_up_sync(0xffffffffu, inc, o);
        if (lane >= o) inc += u;
    }
    if (lane == 31) wsum[wid] = inc;
    __syncthreads();
    if (wid == 0) {
        int s = wsum[lane];
        #pragma unroll
        for (int o = 1; o < 32; o <<= 1) {
            int u = __shfl_up_sync(0xffffffffu, s, o);
            if (lane >= o) s += u;
        }
        wsum[lane] = s;
    }
    __syncthreads();
    int excl = bofs + (wid ? wsum[wid - 1] : 0) + inc - v;
    if (i < NN) { g_off[i] = excl; g_cursor[i] = excl; }
}

// ---------------- 3) scatter (coalesced, packed 16B records, re-zero deg) ----
__device__ __forceinline__ float edge_w(float s) {
    return __expf(fminf(-s, -0.2f * s));   // exp(-leaky_relu(s, 0.2))
}
__global__ void __launch_bounds__(256) k_scatter(const int* __restrict__ ei) {
    int i = blockIdx.x * blockDim.x + threadIdx.x;
    if (i < NN) g_deg[i] = 0;              // restore invariant for next call
    if (i >= NE / 2) return;               // 2 edges per thread
    int s0, s1, d0, d1;
    if (g_is64) {
        int4 sv = ((const int4*)ei)[i];
        int4 dv = ((const int4*)ei)[NE / 2 + i];
        s0 = sv.x; s1 = sv.z; d0 = dv.x; d1 = dv.z;
    } else {
        int2 sv = ((const int2*)ei)[i];
        int2 dv = ((const int2*)ei)[NE / 2 + i];
        s0 = sv.x; s1 = sv.y; d0 = dv.x; d1 = dv.y;
    }
    float4 a0 = g_ssrc[s0], b0 = g_sdst[d0];
    float4 a1 = g_ssrc[s1], b1 = g_sdst[d1];

    __half2 w001 = __floats2half2_rn(edge_w(a0.x + b0.x), edge_w(a0.y + b0.y));
    __half2 w023 = __floats2half2_rn(edge_w(a0.z + b0.z), edge_w(a0.w + b0.w));
    __half2 w101 = __floats2half2_rn(edge_w(a1.x + b1.x), edge_w(a1.y + b1.y));
    __half2 w123 = __floats2half2_rn(edge_w(a1.z + b1.z), edge_w(a1.w + b1.w));

    int p0 = atomicAdd(&g_cursor[s0], 1);
    int p1 = atomicAdd(&g_cursor[s1], 1);

    int4 r0, r1;
    r0.x = *reinterpret_cast<int*>(&w001); r0.y = *reinterpret_cast<int*>(&w023);
    r0.z = d0; r0.w = 0;
    r1.x = *reinterpret_cast<int*>(&w101); r1.y = *reinterpret_cast<int*>(&w123);
    r1.z = d1; r1.w = 0;
    g_edges[p0] = r0;
    g_edges[p1] = r1;
}

// ---------------- 4) aggregation: fp32 x gather, fp16 weights, chunk-4 -------
__global__ void __launch_bounds__(256, 4) k_agg(const float* __restrict__ x,
                                                const float* __restrict__ wp,
                                                float* __restrict__ out) {
    int gw   = (blockIdx.x * blockDim.x + threadIdx.x) >> 5;
    int lane = threadIdx.x & 31;
    if (gw >= NN) return;
    int beg = g_off[gw];
    int n   = g_off[gw + 1] - beg;
    int f = lane * 4;
    const int4* ep = g_edges + beg;
    const int4 zrec = make_int4(0, 0, 0, 0);

    u64 acc[HH][2];
    #pragma unroll
    for (int h = 0; h < HH; h++) { acc[h][0] = 0ull; acc[h][1] = 0ull; }
    u64 rs01 = 0ull, rs23 = 0ull;

    int4 r[4];
    #pragma unroll
    for (int k = 0; k < 4; k++) r[k] = (k < n) ? __ldcs(ep + k) : zrec;

    for (int c = 0; c < n; c += 4) {
        // 4 independent fp32 x gathers (16B/lane) — register pairs feed ffma2 directly
        ulonglong2 xr[4];
        #pragma unroll
        for (int k = 0; k < 4; k++)
            xr[k] = __ldg((const ulonglong2*)(x + (size_t)r[k].z * FF + f));
        // math on edge k, then immediately reload r[k] for the next chunk
        #pragma unroll
        for (int k = 0; k < 4; k++) {
            __half2 hw01 = *reinterpret_cast<__half2*>(&r[k].x);
            __half2 hw23 = *reinterpret_cast<__half2*>(&r[k].y);
            float2 w01 = __half22float2(hw01);
            float2 w23 = __half22float2(hw23);
            rs01 = fadd2(rs01, pack2(w01.x, w01.y));
            rs23 = fadd2(rs23, pack2(w23.x, w23.y));
            u64 xv01 = xr[k].x;                 // already packed fp32x2
            u64 xv23 = xr[k].y;
            u64 p0 = dup2(w01.x), p1 = dup2(w01.y), p2 = dup2(w23.x), p3 = dup2(w23.y);
            acc[0][0] = ffma2(p0, xv01, acc[0][0]); acc[0][1] = ffma2(p0, xv23, acc[0][1]);
            acc[1][0] = ffma2(p1, xv01, acc[1][0]); acc[1][1] = ffma2(p1, xv23, acc[1][1]);
            acc[2][0] = ffma2(p2, xv01, acc[2][0]); acc[2][1] = ffma2(p2, xv23, acc[2][1]);
            acc[3][0] = ffma2(p3, xv01, acc[3][0]); acc[3][1] = ffma2(p3, xv23, acc[3][1]);
            int idx = c + 4 + k;
            r[k] = (idx < n) ? __ldcs(ep + idx) : zrec;
        }
    }

    float rs0, rs1, rs2, rs3;
    unpk2(rs01, rs0, rs1); unpk2(rs23, rs2, rs3);
    float inv[HH] = {1.0f / rs0, 1.0f / rs1, 1.0f / rs2, 1.0f / rs3};

    size_t base = (size_t)gw * FF + f;
    #pragma unroll
    for (int h = 0; h < HH; h++) {
        float4 wv = *(const float4*)(wp + h * FF + f);
        float a0, a1, a2, a3;
        unpk2(acc[h][0], a0, a1); unpk2(acc[h][1], a2, a3);
        __stcs((float4*)(out + (size_t)h * NN * FF + base),
            make_float4(a0 * wv.x * inv[h], a1 * wv.y * inv[h],
                        a2 * wv.z * inv[h], a3 * wv.w * inv[h]));
    }
}

// ---------------- launch -----------------------------------------------------
extern "C" void kernel_launch(void* const* d_in, const int* in_sizes, int n_in,
                              void* d_out, int out_size) {
    const float* x  = (const float*)d_in[0];
    const float* wp = (const float*)d_in[1];
    const float* ap = (const float*)d_in[2];
    const int*   ei = (const int*)d_in[3];
    float* out = (float*)d_out;

    const int TB = 256;
    k_prep<<<NODE_BLOCKS + HIST_BLOCKS, TB>>>(x, wp, ap, ei);
    k_scan<<<NBLK, 1024>>>();
    k_scatter<<<(NE / 2 + TB - 1) / TB, TB>>>(ei);
    k_agg<<<NODE_BLOCKS, TB>>>(x, wp, out);
}